// round 14
// baseline (speedup 1.0000x reference)
#include <cuda_runtime.h>
#include <cuda_bf16.h>
#include <math.h>
#include <stdint.h>

#define NMAX 34816
#define EMAX 557056
#define LMAX 56

// ---------------- device state ----------------
__device__ float g_h[NMAX * 64];
__device__ float g_z[NMAX * 64];
__device__ float g_y[NMAX * 64];
__device__ int g_cnt[NMAX];
__device__ int g_off[NMAX + 1];
__device__ int g_cur[NMAX];
__device__ int g_src[EMAX];
// pre-swizzled bf16 weight operands (hi/lo split), per layer 8192 elems each
__device__ unsigned short g_W1h[LMAX * 8192];
__device__ unsigned short g_W1l[LMAX * 8192];
__device__ unsigned short g_W2h[LMAX * 8192];
__device__ unsigned short g_W2l[LMAX * 8192];

#define SW(x) ((x) ^ (((x) >> 3) & 0x70))

// ---------------- helpers ----------------
__device__ __forceinline__ uint32_t smem_u32(const void* p) {
    uint32_t a;
    asm("{ .reg .u64 t; cvta.to.shared.u64 t, %1; cvt.u32.u64 %0, t; }" : "=r"(a) : "l"(p));
    return a;
}
__device__ __forceinline__ void ldsm4(uint32_t* r, uint32_t addr) {
    asm volatile("ldmatrix.sync.aligned.m8n8.x4.shared.b16 {%0,%1,%2,%3}, [%4];"
                 : "=r"(r[0]), "=r"(r[1]), "=r"(r[2]), "=r"(r[3]) : "r"(addr) : "memory");
}
__device__ __forceinline__ void mma16816(float* d, const uint32_t* a, uint32_t b0, uint32_t b1) {
    asm volatile("mma.sync.aligned.m16n8k16.row.col.f32.bf16.bf16.f32 "
                 "{%0,%1,%2,%3}, {%4,%5,%6,%7}, {%8,%9}, {%0,%1,%2,%3};"
                 : "+f"(d[0]), "+f"(d[1]), "+f"(d[2]), "+f"(d[3])
                 : "r"(a[0]), "r"(a[1]), "r"(a[2]), "r"(a[3]), "r"(b0), "r"(b1));
}
__device__ __forceinline__ uint32_t packbf(float lo, float hi) {
    uint32_t r;
    asm("cvt.rn.bf16x2.f32 %0, %1, %2;" : "=r"(r) : "f"(hi), "f"(lo));
    return r;
}
__device__ __forceinline__ float bfhi(float x) {
    return __bfloat162float(__float2bfloat16(x));
}
__device__ __forceinline__ float ex2f(float x) {
    float y;
    asm("ex2.approx.f32 %0, %1;" : "=f"(y) : "f"(x));
    return y;
}
__device__ __forceinline__ float warpSum(float v) {
#pragma unroll
    for (int o = 16; o; o >>= 1) v += __shfl_xor_sync(0xffffffffu, v, o);
    return v;
}
__device__ __forceinline__ float quadSum(float v) {
    v += __shfl_xor_sync(0xffffffffu, v, 1);
    v += __shfl_xor_sync(0xffffffffu, v, 2);
    return v;
}

// ---------------- CSR build ----------------
__global__ void zero_kernel(int N) {
    int i = blockIdx.x * blockDim.x + threadIdx.x;
    if (i < N) g_cnt[i] = 0;
}
__global__ void count_kernel(const int* __restrict__ dst, int E) {
    int e = blockIdx.x * blockDim.x + threadIdx.x;
    if (e < E) atomicAdd(&g_cnt[dst[e]], 1);
}
__global__ void scan_kernel(int N) {
    __shared__ int s[1024];
    int t = threadIdx.x;
    int CH = (N + 1023) / 1024;
    int beg = t * CH;
    int end = beg + CH; if (end > N) end = N;
    if (beg > N) beg = N;
    int sum = 0;
    for (int i = beg; i < end; i++) sum += g_cnt[i];
    s[t] = sum;
    __syncthreads();
#pragma unroll
    for (int d = 1; d < 1024; d <<= 1) {
        int v = (t >= d) ? s[t - d] : 0;
        __syncthreads();
        if (t >= d) s[t] += v;
        __syncthreads();
    }
    int run = (t == 0) ? 0 : s[t - 1];
    for (int i = beg; i < end; i++) {
        g_off[i] = run;
        g_cur[i] = run;
        run += g_cnt[i];
    }
    if (t == 1023) g_off[N] = s[1023];
}
__global__ void scatter_kernel(const int* __restrict__ src, const int* __restrict__ dst, int E) {
    int e = blockIdx.x * blockDim.x + threadIdx.x;
    if (e < E) {
        int pos = atomicAdd(&g_cur[dst[e]], 1);
        g_src[pos] = src[e];
    }
}

// ---------------- weight prep ----------------
__global__ void prep_kernel(const float* __restrict__ W1, const float* __restrict__ W2) {
    int i = blockIdx.x * blockDim.x + threadIdx.x;
    int total = LMAX * 8192;
    if (i < total) {
        int l = i >> 13, r = i & 8191;
        int k = r >> 7, n = r & 127;  // W1[l][k][n]
        float w = W1[l * 8192 + k * 128 + n];
        __nv_bfloat16 hb = __float2bfloat16(w);
        float hf = __bfloat162float(hb);
        __nv_bfloat16 lb = __float2bfloat16(w - hf);
        uint32_t byte = SW((uint32_t)n * 128u + (uint32_t)k * 2u);
        g_W1h[l * 8192 + (byte >> 1)] = __bfloat16_as_ushort(hb);
        g_W1l[l * 8192 + (byte >> 1)] = __bfloat16_as_ushort(lb);
    } else if (i < 2 * total) {
        i -= total;
        int l = i >> 13, r = i & 8191;
        int k = r >> 6, n = r & 63;   // W2[l][k][n]
        float w = W2[l * 8192 + k * 64 + n];
        __nv_bfloat16 hb = __float2bfloat16(w);
        float hf = __bfloat162float(hb);
        __nv_bfloat16 lb = __float2bfloat16(w - hf);
        int half = k >> 6;
        uint32_t byte = SW((uint32_t)n * 128u + (uint32_t)(k & 63) * 2u);
        g_W2h[l * 8192 + half * 4096 + (byte >> 1)] = __bfloat16_as_ushort(hb);
        g_W2l[l * 8192 + half * 4096 + (byte >> 1)] = __bfloat16_as_ushort(lb);
    }
}

// ---------------- Encoder ----------------
__global__ void enc_kernel(const float* __restrict__ x, const float* __restrict__ W,
                           const float* __restrict__ b, int N) {
    int i = blockIdx.x * blockDim.x + threadIdx.x;
    if (i >= N * 64) return;
    int n = i >> 6, c = i & 63;
    g_z[i] = fmaf(x[n * 3], W[c], fmaf(x[n * 3 + 1], W[64 + c], b[c]));
}

// ---------------- Aggregation: one warp per node, float4 half-warp-per-edge ----------
// lanes 0-15 process even edges (4 channels each), lanes 16-31 odd edges;
// per-channel partials combined with shfl_xor(16) at the end (exact reordering).
// eps folded out of loop: exp(t(p+eps)) = exp(tp)*const (cancels); sum w*(p+eps)=sum w*p+eps
template <bool RELU>
__global__ void __launch_bounds__(256) aggr_kernel(const float* __restrict__ t, int layer, int N) {
    int gw = (blockIdx.x * 256 + threadIdx.x) >> 5;
    int lane = threadIdx.x & 31;
    if (gw >= N) return;
    float tl2 = __ldg(&t[layer]) * 1.4426950408889634f;
    const float SHIFT = -5.770780163555854f;  // -4*log2(e); cancels in acc/den ratio
    const float4* __restrict__ z4 = (const float4*)g_z;  // node row = 16 float4
    int ln15 = lane & 15;
    int e0 = lane >> 4;     // half-warp edge selector
    int beg = g_off[gw], end = g_off[gw + 1];
    int nb = end - beg;
    // self term: issue early, consumed at the very end
    float4 zi = z4[(size_t)gw * 16 + ln15];
    float acc0 = 0.f, acc1 = 0.f, acc2c = 0.f, acc3 = 0.f;
    float den0 = 0.f, den1 = 0.f, den2 = 0.f, den3 = 0.f;
#define PROC4(vv) { \
    float p0 = RELU ? fmaxf((vv).x, 0.f) : (vv).x; \
    float p1 = RELU ? fmaxf((vv).y, 0.f) : (vv).y; \
    float p2 = RELU ? fmaxf((vv).z, 0.f) : (vv).z; \
    float p3 = RELU ? fmaxf((vv).w, 0.f) : (vv).w; \
    float E0 = ex2f(fmaf(tl2, p0, SHIFT)); \
    float E1 = ex2f(fmaf(tl2, p1, SHIFT)); \
    float E2 = ex2f(fmaf(tl2, p2, SHIFT)); \
    float E3 = ex2f(fmaf(tl2, p3, SHIFT)); \
    den0 += E0; den1 += E1; den2 += E2; den3 += E3; \
    acc0 = fmaf(E0, p0, acc0); acc1 = fmaf(E1, p1, acc1); \
    acc2c = fmaf(E2, p2, acc2c); acc3 = fmaf(E3, p3, acc3); }
    int pairs = nb >> 1;
    int bigPairs = pairs & ~3;
    int j = 0;
    int idx[8];
    if (bigPairs > 0) {
#pragma unroll
        for (int b = 0; b < 8; b++) idx[b] = g_src[beg + b];
    }
    while (j < bigPairs) {
        float4 v0 = z4[(size_t)idx[0 + e0] * 16 + ln15];
        float4 v1 = z4[(size_t)idx[2 + e0] * 16 + ln15];
        float4 v2 = z4[(size_t)idx[4 + e0] * 16 + ln15];
        float4 v3 = z4[(size_t)idx[6 + e0] * 16 + ln15];
        int jn = j + 4;
        if (jn < bigPairs) {
#pragma unroll
            for (int b = 0; b < 8; b++) idx[b] = g_src[beg + 2 * jn + b];
        }
        PROC4(v0) PROC4(v1) PROC4(v2) PROC4(v3)
        j = jn;
    }
    for (; j < pairs; j++) {
        int s = g_src[beg + 2 * j + e0];
        float4 v = z4[(size_t)s * 16 + ln15];
        PROC4(v)
    }
    if (nb & 1) {
        if (lane < 16) {
            int s = g_src[end - 1];
            float4 v = z4[(size_t)s * 16 + ln15];
            PROC4(v)
        }
    }
#undef PROC4
    // combine the two half-warp partial sums (lane <-> lane^16)
    acc0 += __shfl_xor_sync(0xffffffffu, acc0, 16);
    acc1 += __shfl_xor_sync(0xffffffffu, acc1, 16);
    acc2c += __shfl_xor_sync(0xffffffffu, acc2c, 16);
    acc3 += __shfl_xor_sync(0xffffffffu, acc3, 16);
    den0 += __shfl_xor_sync(0xffffffffu, den0, 16);
    den1 += __shfl_xor_sync(0xffffffffu, den1, 16);
    den2 += __shfl_xor_sync(0xffffffffu, den2, 16);
    den3 += __shfl_xor_sync(0xffffffffu, den3, 16);
    if (lane < 16) {
        float4 y = zi;
        if (nb > 0) {
            y.x += acc0 / den0 + 1e-7f;
            y.y += acc1 / den1 + 1e-7f;
            y.z += acc2c / den2 + 1e-7f;
            y.w += acc3 / den3 + 1e-7f;
        }
        ((float4*)g_y)[(size_t)gw * 16 + ln15] = y;
    }
}

// ---------------- MLP: mma.sync, 512 thr (1 group/warp), fused next-layer prenorm --------
#define SM2_W1H 0
#define SM2_W1L 16384
#define SM2_W2H 32768
#define SM2_W2L 49152
#define SM2_SB1 65536
#define SM2_SLG 66048
#define SM2_SLB 67072
#define SM2_SB2 67584
#define SM2_SNG 67840
#define SM2_SNB 68096
#define SM2_TOTAL 68352

__global__ void __launch_bounds__(512, 1) mlp_kernel(
    const float* __restrict__ b1, const float* __restrict__ lg,
    const float* __restrict__ lb, const float* __restrict__ b2,
    const float* __restrict__ ng, const float* __restrict__ nb,
    int layer, int N, int add, int writez) {
    extern __shared__ char smem[];
    uint32_t sbase = smem_u32(smem);
    int tid = threadIdx.x;
    int w = tid >> 5, lane = tid & 31;

    {
        const uint4* s1h = (const uint4*)(g_W1h + layer * 8192);
        const uint4* s1l = (const uint4*)(g_W1l + layer * 8192);
        const uint4* s2h = (const uint4*)(g_W2h + layer * 8192);
        const uint4* s2l = (const uint4*)(g_W2l + layer * 8192);
        uint4* d1h = (uint4*)(smem + SM2_W1H);
        uint4* d1l = (uint4*)(smem + SM2_W1L);
        uint4* d2h = (uint4*)(smem + SM2_W2H);
        uint4* d2l = (uint4*)(smem + SM2_W2L);
        for (int i = tid; i < 1024; i += 512) {
            d1h[i] = s1h[i]; d1l[i] = s1l[i]; d2h[i] = s2h[i]; d2l[i] = s2l[i];
        }
    }
    float* sb1 = (float*)(smem + SM2_SB1);
    float* slg = (float*)(smem + SM2_SLG);
    float* slb = (float*)(smem + SM2_SLB);
    float* sb2 = (float*)(smem + SM2_SB2);
    float* sng = (float*)(smem + SM2_SNG);
    float* snb = (float*)(smem + SM2_SNB);
    if (tid < 128) { sb1[tid] = b1[tid]; slg[tid] = lg[tid]; slb[tid] = lb[tid]; }
    if (tid < 64) {
        sb2[tid] = b2[tid];
        sng[tid] = writez ? ng[tid] : 0.f;
        snb[tid] = writez ? nb[tid] : 0.f;
    }

    int q = lane & 3;
    int g = lane >> 2;
    int nGroups = N >> 4;
    int grp = blockIdx.x * 16 + w;
    bool act = grp < nGroups;
    int n0 = grp << 4;

    // prefetch first y batch BEFORE the sync so it overlaps weight staging
    const float2* yr1 = (const float2*)(g_y + (size_t)(n0 + g) * 64);
    const float2* yr2 = (const float2*)(g_y + (size_t)(n0 + g + 8) * 64);
    float2 fa0, fa1, fb0, fb1;
    if (act) { fa0 = yr1[q]; fa1 = yr1[4 + q]; fb0 = yr2[q]; fb1 = yr2[4 + q]; }

    __syncthreads();
    if (!act) return;

    // ldmatrix B addressing
    int lane7 = lane & 7;
    int laneb3 = (lane >> 3) & 1;
    int laneb4 = lane >> 4;
    uint32_t mask = (uint32_t)lane7 << 4;
    uint32_t bRow = (uint32_t)(laneb4 * 8 + lane7) * 128u;
    uint32_t bSeg = (uint32_t)laneb3 * 16u;

    float2* h2 = (float2*)g_h;
    float2* z2 = (float2*)g_z;

    // ---- GEMM1: C1[16x128] = A1[16x64] @ W1T^T (rolling y prefetch) ----
    float acc[16][4];
#pragma unroll
    for (int i = 0; i < 16; i++) { acc[i][0] = 0.f; acc[i][1] = 0.f; acc[i][2] = 0.f; acc[i][3] = 0.f; }
#pragma unroll
    for (int kk = 0; kk < 4; kk++) {
        float2 p0 = fa0, p1 = fa1, p2 = fb0, p3 = fb1;
        if (kk < 3) {
            fa0 = yr1[8 * (kk + 1) + q];
            fa1 = yr1[8 * (kk + 1) + 4 + q];
            fb0 = yr2[8 * (kk + 1) + q];
            fb1 = yr2[8 * (kk + 1) + 4 + q];
        }
        float h00 = bfhi(p0.x), h01 = bfhi(p0.y);
        float h10 = bfhi(p1.x), h11 = bfhi(p1.y);
        float h20 = bfhi(p2.x), h21 = bfhi(p2.y);
        float h30 = bfhi(p3.x), h31 = bfhi(p3.y);
        uint32_t ah[4], al[4];
        ah[0] = packbf(h00, h01); ah[1] = packbf(h20, h21);
        ah[2] = packbf(h10, h11); ah[3] = packbf(h30, h31);
        al[0] = packbf(p0.x - h00, p0.y - h01);
        al[1] = packbf(p2.x - h20, p2.y - h21);
        al[2] = packbf(p1.x - h10, p1.y - h11);
        al[3] = packbf(p3.x - h30, p3.y - h31);
#pragma unroll
        for (int n16 = 0; n16 < 8; n16++) {
            uint32_t bo = (uint32_t)n16 * 2048u + bRow + (((uint32_t)kk * 32u + bSeg) ^ mask);
            uint32_t bh[4], bl[4];
            ldsm4(bh, sbase + SM2_W1H + bo);
            ldsm4(bl, sbase + SM2_W1L + bo);
            float* c0 = acc[2 * n16];
            float* c1 = acc[2 * n16 + 1];
            mma16816(c0, ah, bh[0], bh[1]);
            mma16816(c1, ah, bh[2], bh[3]);
            mma16816(c0, ah, bl[0], bl[1]);
            mma16816(c1, ah, bl[2], bl[3]);
            mma16816(c0, al, bh[0], bh[1]);
            mma16816(c1, al, bh[2], bh[3]);
        }
    }
    // ---- epilogue1: bias + LN + relu, in-register (quad reduce) ----
    {
        float sA = 0.f, sB = 0.f, qA = 0.f, qB = 0.f;
#pragma unroll
        for (int idx = 0; idx < 16; idx++) {
            int col = idx * 8 + 2 * q;
            float bb0 = sb1[col], bb1 = sb1[col + 1];
            acc[idx][0] += bb0; acc[idx][1] += bb1;
            acc[idx][2] += bb0; acc[idx][3] += bb1;
            sA += acc[idx][0] + acc[idx][1];
            sB += acc[idx][2] + acc[idx][3];
            qA = fmaf(acc[idx][0], acc[idx][0], qA);
            qA = fmaf(acc[idx][1], acc[idx][1], qA);
            qB = fmaf(acc[idx][2], acc[idx][2], qB);
            qB = fmaf(acc[idx][3], acc[idx][3], qB);
        }
        sA = quadSum(sA); sB = quadSum(sB);
        qA = quadSum(qA); qB = quadSum(qB);
        float meanA = sA * (1.0f / 128.0f);
        float meanB = sB * (1.0f / 128.0f);
        float varA = qA * (1.0f / 128.0f) - meanA * meanA;
        float varB = qB * (1.0f / 128.0f) - meanB * meanB;
        float rstdA = rsqrtf(varA + 1e-5f);
        float rstdB = rsqrtf(varB + 1e-5f);
#pragma unroll
        for (int idx = 0; idx < 16; idx++) {
            int col = idx * 8 + 2 * q;
            float g0 = slg[col], g1 = slg[col + 1];
            float bb0 = slb[col], bb1 = slb[col + 1];
            acc[idx][0] = fmaxf(fmaf((acc[idx][0] - meanA) * rstdA, g0, bb0), 0.f);
            acc[idx][1] = fmaxf(fmaf((acc[idx][1] - meanA) * rstdA, g1, bb1), 0.f);
            acc[idx][2] = fmaxf(fmaf((acc[idx][2] - meanB) * rstdB, g0, bb0), 0.f);
            acc[idx][3] = fmaxf(fmaf((acc[idx][3] - meanB) * rstdB, g1, bb1), 0.f);
        }
    }
    // ---- GEMM2: C2[16x64] = A2[16x128] @ W2T^T ; A2 frags from acc regs ----
    float acc2[8][4];
#pragma unroll
    for (int i = 0; i < 8; i++) { acc2[i][0] = 0.f; acc2[i][1] = 0.f; acc2[i][2] = 0.f; acc2[i][3] = 0.f; }
#pragma unroll
    for (int kk = 0; kk < 8; kk++) {
        int i0 = 2 * kk, i1 = 2 * kk + 1;
        float h00 = bfhi(acc[i0][0]), h01 = bfhi(acc[i0][1]);
        float h20 = bfhi(acc[i0][2]), h21 = bfhi(acc[i0][3]);
        float h10 = bfhi(acc[i1][0]), h11 = bfhi(acc[i1][1]);
        float h30 = bfhi(acc[i1][2]), h31 = bfhi(acc[i1][3]);
        uint32_t ah[4], al[4];
        ah[0] = packbf(h00, h01); ah[1] = packbf(h20, h21);
        ah[2] = packbf(h10, h11); ah[3] = packbf(h30, h31);
        al[0] = packbf(acc[i0][0] - h00, acc[i0][1] - h01);
        al[1] = packbf(acc[i0][2] - h20, acc[i0][3] - h21);
        al[2] = packbf(acc[i1][0] - h10, acc[i1][1] - h11);
        al[3] = packbf(acc[i1][2] - h30, acc[i1][3] - h31);
        uint32_t halfW = (kk < 4) ? 0u : 8192u;
        uint32_t kk2 = (uint32_t)(kk & 3);
#pragma unroll
        for (int n16 = 0; n16 < 4; n16++) {
            uint32_t bo = (uint32_t)n16 * 2048u + bRow + ((kk2 * 32u + bSeg) ^ mask) + halfW;
            uint32_t bh[4], bl[4];
            ldsm4(bh, sbase + SM2_W2H + bo);
            ldsm4(bl, sbase + SM2_W2L + bo);
            float* c0 = acc2[2 * n16];
            float* c1 = acc2[2 * n16 + 1];
            mma16816(c0, ah, bh[0], bh[1]);
            mma16816(c1, ah, bh[2], bh[3]);
            mma16816(c0, ah, bl[0], bl[1]);
            mma16816(c1, ah, bl[2], bl[3]);
            mma16816(c0, al, bh[0], bh[1]);
            mma16816(c1, al, bh[2], bh[3]);
        }
    }
    // ---- epilogue2: bias + residual -> h ; fused next-layer prenorm -> z ----
    {
        int nodeA = n0 + g, nodeB = n0 + g + 8;
        float sA = 0.f, sB = 0.f, qA = 0.f, qB = 0.f;
#pragma unroll
        for (int idx = 0; idx < 8; idx++) {
            int col = idx * 8 + 2 * q;
            float bb0 = sb2[col], bb1 = sb2[col + 1];
            float oA0 = acc2[idx][0] + bb0, oA1 = acc2[idx][1] + bb1;
            float oB0 = acc2[idx][2] + bb0, oB1 = acc2[idx][3] + bb1;
            int iA = nodeA * 32 + (col >> 1);
            int iB = nodeB * 32 + (col >> 1);
            if (add) {
                float2 rA = h2[iA], rB = h2[iB];
                oA0 += rA.x; oA1 += rA.y;
                oB0 += rB.x; oB1 += rB.y;
            }
            h2[iA] = make_float2(oA0, oA1);
            h2[iB] = make_float2(oB0, oB1);
            acc2[idx][0] = oA0; acc2[idx][1] = oA1;
            acc2[idx][2] = oB0; acc2[idx][3] = oB1;
            sA += oA0 + oA1; sB += oB0 + oB1;
            qA = fmaf(oA0, oA0, qA); qA = fmaf(oA1, oA1, qA);
            qB = fmaf(oB0, oB0, qB); qB = fmaf(oB1, oB1, qB);
        }
        if (writez) {
            sA = quadSum(sA); sB = quadSum(sB);
            qA = quadSum(qA); qB = quadSum(qB);
            float meanA = sA * (1.0f / 64.0f);
            float meanB = sB * (1.0f / 64.0f);
            float varA = qA * (1.0f / 64.0f) - meanA * meanA;
            float varB = qB * (1.0f / 64.0f) - meanB * meanB;
            float rstdA = rsqrtf(varA + 1e-5f);
            float rstdB = rsqrtf(varB + 1e-5f);
#pragma unroll
            for (int idx = 0; idx < 8; idx++) {
                int col = idx * 8 + 2 * q;
                float g0 = sng[col], g1 = sng[col + 1];
                float bb0 = snb[col], bb1 = snb[col + 1];
                float2 zA, zB;
                zA.x = fmaxf(fmaf((acc2[idx][0] - meanA) * rstdA, g0, bb0), 0.f);
                zA.y = fmaxf(fmaf((acc2[idx][1] - meanA) * rstdA, g1, bb1), 0.f);
                zB.x = fmaxf(fmaf((acc2[idx][2] - meanB) * rstdB, g0, bb0), 0.f);
                zB.y = fmaxf(fmaf((acc2[idx][3] - meanB) * rstdB, g1, bb1), 0.f);
                z2[nodeA * 32 + (col >> 1)] = zA;
                z2[nodeB * 32 + (col >> 1)] = zB;
            }
        }
    }
}

// ---------------- Head: LN -> pool -> fc -> bn -> l2norm ----------------
__global__ void __launch_bounds__(256) head_kernel(
    const float* __restrict__ ng, const float* __restrict__ nb,
    const float* __restrict__ fcW, const float* __restrict__ fcb,
    const float* __restrict__ bg, const float* __restrict__ bb,
    const float* __restrict__ bm, const float* __restrict__ bv,
    float* __restrict__ out, int NP) {
    __shared__ float shp[17 * 64];
    __shared__ float spool[6 * 64];
    __shared__ float sf[1536];
    __shared__ float sred[8];
    __shared__ float sinv;
    int p = blockIdx.x;
    int tid = threadIdx.x;
    int w = tid >> 5, lane = tid & 31;
    const float2* __restrict__ h2 = (const float2*)g_h;
    float2 gg = ((const float2*)ng)[lane];
    float2 gb = ((const float2*)nb)[lane];
    for (int i = w; i < 17; i += 8) {
        float2 v = h2[(p * 17 + i) * 32 + lane];
        float mean = warpSum(v.x + v.y) * (1.0f / 64.0f);
        float dx = v.x - mean, dy = v.y - mean;
        float var = warpSum(dx * dx + dy * dy) * (1.0f / 64.0f);
        float rstd = rsqrtf(var + 1e-5f);
        shp[i * 64 + 2 * lane]     = fmaxf(fmaf(dx * rstd, gg.x, gb.x), 0.0f);
        shp[i * 64 + 2 * lane + 1] = fmaxf(fmaf(dy * rstd, gg.y, gb.y), 0.0f);
    }
    __syncthreads();
    {
        const int ga[6] = {0, 0, 11, 0, 5, 11};
        const int gbx[6] = {17, 11, 17, 5, 11, 17};
        for (int i = tid; i < 384; i += 256) {
            int s = i >> 6, c = i & 63;
            float acc = 0;
            for (int kp = ga[s]; kp < gbx[s]; kp++) acc += shp[kp * 64 + c];
            spool[i] = acc / (float)(gbx[s] - ga[s]);
        }
    }
    __syncthreads();
    float sq = 0;
#pragma unroll
    for (int s = 0; s < 6; s++) {
        int o = s * 256 + tid;
        float acc = fcb[o];
        const float* wp = fcW + s * 16384 + tid;
        const float* pp = spool + s * 64;
#pragma unroll 8
        for (int c = 0; c < 64; c++) acc = fmaf(pp[c], wp[c * 256], acc);
        float val = fmaf((acc - bm[o]) * rsqrtf(bv[o] + 1e-5f), bg[o], bb[o]);
        sf[o] = val;
        sq = fmaf(val, val, sq);
    }
    sq = warpSum(sq);
    if (lane == 0) sred[w] = sq;
    __syncthreads();
    if (tid == 0) {
        float tot = 0;
#pragma unroll
        for (int i = 0; i < 8; i++) tot += sred[i];
        sinv = 1.0f / fmaxf(sqrtf(tot), 1e-12f);
    }
    __syncthreads();
    float inv = sinv;
#pragma unroll
    for (int s = 0; s < 6; s++) {
        int o = s * 256 + tid;
        out[p * 1536 + o] = sf[o] * inv;
    }
}

// ---------------- Host orchestration ----------------
extern "C" void kernel_launch(void* const* d_in, const int* in_sizes, int n_in,
                              void* d_out, int out_size) {
    const float* x      = (const float*)d_in[0];
    const int*   ei     = (const int*)d_in[1];
    const float* enc_W  = (const float*)d_in[2];
    const float* enc_b  = (const float*)d_in[3];
    const float* t      = (const float*)d_in[4];
    const float* mlp_W1 = (const float*)d_in[5];
    const float* mlp_b1 = (const float*)d_in[6];
    const float* ln_g   = (const float*)d_in[7];
    const float* ln_b   = (const float*)d_in[8];
    const float* mlp_W2 = (const float*)d_in[9];
    const float* mlp_b2 = (const float*)d_in[10];
    const float* norm_g = (const float*)d_in[11];
    const float* norm_b = (const float*)d_in[12];
    const float* fc_W   = (const float*)d_in[13];
    const float* fc_b   = (const float*)d_in[14];
    const float* bn_g   = (const float*)d_in[15];
    const float* bn_b   = (const float*)d_in[16];
    const float* bn_m   = (const float*)d_in[17];
    const float* bn_v   = (const float*)d_in[18];
    float* out = (float*)d_out;

    int N = in_sizes[0] / 3;
    int E = in_sizes[1] / 2;
    int NP = N / 17;
    const int L = 56;

    cudaFuncSetAttribute(mlp_kernel, cudaFuncAttributeMaxDynamicSharedMemorySize, SM2_TOTAL);

    // CSR build (dst-sorted)
    zero_kernel<<<(N + 255) / 256, 256>>>(N);
    count_kernel<<<(E + 255) / 256, 256>>>(ei + E, E);
    scan_kernel<<<1, 1024>>>(N);
    scatter_kernel<<<(E + 255) / 256, 256>>>(ei, ei + E, E);

    // weight prep (bf16 split + swizzle, all layers)
    prep_kernel<<<(2 * LMAX * 8192 + 255) / 256, 256>>>(mlp_W1, mlp_W2);

    // Encoder -> z (layer 0 aggregates raw encoder output; needs relu)
    enc_kernel<<<(N * 64 + 255) / 256, 256>>>(x, enc_W, enc_b, N);

    const int MGRID = 148;
    int aggrBlocks = (N + 7) / 8;   // one warp per node

    for (int l = 0; l < L; l++) {
        if (l == 0) aggr_kernel<true><<<aggrBlocks, 256>>>(t, l, N);
        else        aggr_kernel<false><<<aggrBlocks, 256>>>(t, l, N);
        int last = (l == L - 1);
        mlp_kernel<<<MGRID, 512, SM2_TOTAL>>>(
            mlp_b1 + l * 128, ln_g + l * 128, ln_b + l * 128, mlp_b2 + l * 64,
            norm_g + (last ? 0 : (l + 1) * 64), norm_b + (last ? 0 : (l + 1) * 64),
            l, N, l != 0, !last);
    }

    // Head (applies final LN with layer-0 norm params internally)
    head_kernel<<<NP, 256>>>(norm_g, norm_b, fc_W, fc_b, bn_g, bn_b, bn_m, bn_v, out, NP);
}

// round 16
// speedup vs baseline: 1.3918x; 1.3918x over previous
#include <cuda_runtime.h>
#include <cuda_bf16.h>
#include <math.h>
#include <stdint.h>

#define NMAX 34816
#define EMAX 557056
#define LMAX 56

// ---------------- device state ----------------
__device__ float g_h[NMAX * 64];
__device__ float g_z[NMAX * 64];
__device__ float g_y[NMAX * 64];
__device__ int g_cnt[NMAX];
__device__ int g_off[NMAX + 1];
__device__ int g_cur[NMAX];
__device__ int g_src[EMAX];
__device__ int g_dcnt[256];
__device__ int g_dcur[256];
__device__ int g_perm[NMAX];
// pre-swizzled bf16 weight operands (hi/lo split), per layer 8192 elems each
__device__ unsigned short g_W1h[LMAX * 8192];
__device__ unsigned short g_W1l[LMAX * 8192];
__device__ unsigned short g_W2h[LMAX * 8192];
__device__ unsigned short g_W2l[LMAX * 8192];

#define SW(x) ((x) ^ (((x) >> 3) & 0x70))

// ---------------- helpers ----------------
__device__ __forceinline__ uint32_t smem_u32(const void* p) {
    uint32_t a;
    asm("{ .reg .u64 t; cvta.to.shared.u64 t, %1; cvt.u32.u64 %0, t; }" : "=r"(a) : "l"(p));
    return a;
}
__device__ __forceinline__ void ldsm4(uint32_t* r, uint32_t addr) {
    asm volatile("ldmatrix.sync.aligned.m8n8.x4.shared.b16 {%0,%1,%2,%3}, [%4];"
                 : "=r"(r[0]), "=r"(r[1]), "=r"(r[2]), "=r"(r[3]) : "r"(addr) : "memory");
}
__device__ __forceinline__ void mma16816(float* d, const uint32_t* a, uint32_t b0, uint32_t b1) {
    asm volatile("mma.sync.aligned.m16n8k16.row.col.f32.bf16.bf16.f32 "
                 "{%0,%1,%2,%3}, {%4,%5,%6,%7}, {%8,%9}, {%0,%1,%2,%3};"
                 : "+f"(d[0]), "+f"(d[1]), "+f"(d[2]), "+f"(d[3])
                 : "r"(a[0]), "r"(a[1]), "r"(a[2]), "r"(a[3]), "r"(b0), "r"(b1));
}
__device__ __forceinline__ uint32_t packbf(float lo, float hi) {
    uint32_t r;
    asm("cvt.rn.bf16x2.f32 %0, %1, %2;" : "=r"(r) : "f"(hi), "f"(lo));
    return r;
}
__device__ __forceinline__ float bfhi(float x) {
    return __bfloat162float(__float2bfloat16(x));
}
__device__ __forceinline__ float ex2f(float x) {
    float y;
    asm("ex2.approx.f32 %0, %1;" : "=f"(y) : "f"(x));
    return y;
}
__device__ __forceinline__ float warpSum(float v) {
#pragma unroll
    for (int o = 16; o; o >>= 1) v += __shfl_xor_sync(0xffffffffu, v, o);
    return v;
}
__device__ __forceinline__ float quadSum(float v) {
    v += __shfl_xor_sync(0xffffffffu, v, 1);
    v += __shfl_xor_sync(0xffffffffu, v, 2);
    return v;
}

// ---------------- CSR build ----------------
__global__ void zero_kernel(int N) {
    int i = blockIdx.x * blockDim.x + threadIdx.x;
    if (i < N) g_cnt[i] = 0;
    if (i < 256) { g_dcnt[i] = 0; }
}
__global__ void count_kernel(const int* __restrict__ dst, int E) {
    int e = blockIdx.x * blockDim.x + threadIdx.x;
    if (e < E) atomicAdd(&g_cnt[dst[e]], 1);
}
__global__ void scan_kernel(int N) {
    __shared__ int s[1024];
    int t = threadIdx.x;
    int CH = (N + 1023) / 1024;
    int beg = t * CH;
    int end = beg + CH; if (end > N) end = N;
    if (beg > N) beg = N;
    int sum = 0;
    for (int i = beg; i < end; i++) sum += g_cnt[i];
    s[t] = sum;
    __syncthreads();
#pragma unroll
    for (int d = 1; d < 1024; d <<= 1) {
        int v = (t >= d) ? s[t - d] : 0;
        __syncthreads();
        if (t >= d) s[t] += v;
        __syncthreads();
    }
    int run = (t == 0) ? 0 : s[t - 1];
    for (int i = beg; i < end; i++) {
        g_off[i] = run;
        g_cur[i] = run;
        run += g_cnt[i];
    }
    if (t == 1023) g_off[N] = s[1023];
}
__global__ void scatter_kernel(const int* __restrict__ src, const int* __restrict__ dst, int E) {
    int e = blockIdx.x * blockDim.x + threadIdx.x;
    if (e < E) {
        int pos = atomicAdd(&g_cur[dst[e]], 1);
        g_src[pos] = src[e];
    }
}
// degree-histogram (descending buckets: high degree -> low bucket index)
__global__ void dcount_kernel(int N) {
    int i = blockIdx.x * blockDim.x + threadIdx.x;
    if (i < N) {
        int d = g_cnt[i]; if (d > 255) d = 255;
        atomicAdd(&g_dcnt[255 - d], 1);
    }
}
__global__ void dscan_kernel() {
    __shared__ int s[256];
    int t = threadIdx.x;
    s[t] = g_dcnt[t];
    __syncthreads();
#pragma unroll
    for (int d = 1; d < 256; d <<= 1) {
        int v = (t >= d) ? s[t - d] : 0;
        __syncthreads();
        if (t >= d) s[t] += v;
        __syncthreads();
    }
    g_dcur[t] = (t == 0) ? 0 : s[t - 1];
}
__global__ void dscatter_kernel(int N) {
    int i = blockIdx.x * blockDim.x + threadIdx.x;
    if (i < N) {
        int d = g_cnt[i]; if (d > 255) d = 255;
        int pos = atomicAdd(&g_dcur[255 - d], 1);
        g_perm[pos] = i;
    }
}

// ---------------- weight prep ----------------
__global__ void prep_kernel(const float* __restrict__ W1, const float* __restrict__ W2) {
    int i = blockIdx.x * blockDim.x + threadIdx.x;
    int total = LMAX * 8192;
    if (i < total) {
        int l = i >> 13, r = i & 8191;
        int k = r >> 7, n = r & 127;  // W1[l][k][n]
        float w = W1[l * 8192 + k * 128 + n];
        __nv_bfloat16 hb = __float2bfloat16(w);
        float hf = __bfloat162float(hb);
        __nv_bfloat16 lb = __float2bfloat16(w - hf);
        uint32_t byte = SW((uint32_t)n * 128u + (uint32_t)k * 2u);
        g_W1h[l * 8192 + (byte >> 1)] = __bfloat16_as_ushort(hb);
        g_W1l[l * 8192 + (byte >> 1)] = __bfloat16_as_ushort(lb);
    } else if (i < 2 * total) {
        i -= total;
        int l = i >> 13, r = i & 8191;
        int k = r >> 6, n = r & 63;   // W2[l][k][n]
        float w = W2[l * 8192 + k * 64 + n];
        __nv_bfloat16 hb = __float2bfloat16(w);
        float hf = __bfloat162float(hb);
        __nv_bfloat16 lb = __float2bfloat16(w - hf);
        int half = k >> 6;
        uint32_t byte = SW((uint32_t)n * 128u + (uint32_t)(k & 63) * 2u);
        g_W2h[l * 8192 + half * 4096 + (byte >> 1)] = __bfloat16_as_ushort(hb);
        g_W2l[l * 8192 + half * 4096 + (byte >> 1)] = __bfloat16_as_ushort(lb);
    }
}

// ---------------- Encoder ----------------
__global__ void enc_kernel(const float* __restrict__ x, const float* __restrict__ W,
                           const float* __restrict__ b, int N) {
    int i = blockIdx.x * blockDim.x + threadIdx.x;
    if (i >= N * 64) return;
    int n = i >> 6, c = i & 63;
    g_z[i] = fmaf(x[n * 3], W[c], fmaf(x[n * 3 + 1], W[64 + c], b[c]));
}

// ---------------- Aggregation: one warp per node (degree-sorted), pipelined idx fetch --
// y = softmax_aggr(relu(z[src])+eps) + z ; fixed-shift softmax; eps folded out of loop:
//   exp(t(p+eps)) = exp(tp)*const (cancels in ratio) ; sum w*(p+eps) = sum w*p + eps
template <bool RELU>
__global__ void __launch_bounds__(256) aggr_kernel(const float* __restrict__ t, int layer, int N) {
    int gw = (blockIdx.x * 256 + threadIdx.x) >> 5;
    int lane = threadIdx.x & 31;
    if (gw >= N) return;
    int node = g_perm[gw];
    float tl2 = __ldg(&t[layer]) * 1.4426950408889634f;
    const float SHIFT = -5.770780163555854f;  // -4*log2(e); cancels in acc/den ratio
    const float2* __restrict__ z2 = (const float2*)g_z;
    int beg = g_off[node], end = g_off[node + 1];
    float acc0 = 0.f, acc1 = 0.f, den0 = 0.f, den1 = 0.f;
#define PROC(vv) { float p0 = RELU ? fmaxf((vv).x, 0.f) : (vv).x; \
                   float p1 = RELU ? fmaxf((vv).y, 0.f) : (vv).y; \
                   float e0 = ex2f(fmaf(tl2, p0, SHIFT)); \
                   float e1 = ex2f(fmaf(tl2, p1, SHIFT)); \
                   den0 += e0; den1 += e1; acc0 = fmaf(e0, p0, acc0); acc1 = fmaf(e1, p1, acc1); }
    int nb = end - beg;
    int jend8 = beg + (nb & ~7);
    int j = beg;
    int idx[8];
    if (j < jend8) {
#pragma unroll
        for (int b = 0; b < 8; b++) idx[b] = g_src[j + b];
    }
    while (j < jend8) {
        float2 v0 = z2[idx[0] * 32 + lane];
        float2 v1 = z2[idx[1] * 32 + lane];
        float2 v2 = z2[idx[2] * 32 + lane];
        float2 v3 = z2[idx[3] * 32 + lane];
        float2 v4 = z2[idx[4] * 32 + lane];
        float2 v5 = z2[idx[5] * 32 + lane];
        float2 v6 = z2[idx[6] * 32 + lane];
        float2 v7 = z2[idx[7] * 32 + lane];
        int jn = j + 8;
        if (jn < jend8) {
#pragma unroll
            for (int b = 0; b < 8; b++) idx[b] = g_src[jn + b];
        }
        PROC(v0) PROC(v1) PROC(v2) PROC(v3) PROC(v4) PROC(v5) PROC(v6) PROC(v7)
        j = jn;
    }
    for (; j < end; j++) {
        int s = g_src[j];
        float2 v = z2[s * 32 + lane];
        PROC(v)
    }
#undef PROC
    float2 zi = z2[node * 32 + lane];
    float y0 = zi.x, y1 = zi.y;
    if (end > beg) { y0 += acc0 / den0 + 1e-7f; y1 += acc1 / den1 + 1e-7f; }
    ((float2*)g_y)[node * 32 + lane] = make_float2(y0, y1);
}

// ---------------- MLP: mma.sync, 512 thr (1 group/warp), fused next-layer prenorm --------
#define SM2_W1H 0
#define SM2_W1L 16384
#define SM2_W2H 32768
#define SM2_W2L 49152
#define SM2_SB1 65536
#define SM2_SLG 66048
#define SM2_SLB 67072
#define SM2_SB2 67584
#define SM2_SNG 67840
#define SM2_SNB 68096
#define SM2_TOTAL 68352

__global__ void __launch_bounds__(512, 1) mlp_kernel(
    const float* __restrict__ b1, const float* __restrict__ lg,
    const float* __restrict__ lb, const float* __restrict__ b2,
    const float* __restrict__ ng, const float* __restrict__ nb,
    int layer, int N, int add, int writez) {
    extern __shared__ char smem[];
    uint32_t sbase = smem_u32(smem);
    int tid = threadIdx.x;
    int w = tid >> 5, lane = tid & 31;

    {
        const uint4* s1h = (const uint4*)(g_W1h + layer * 8192);
        const uint4* s1l = (const uint4*)(g_W1l + layer * 8192);
        const uint4* s2h = (const uint4*)(g_W2h + layer * 8192);
        const uint4* s2l = (const uint4*)(g_W2l + layer * 8192);
        uint4* d1h = (uint4*)(smem + SM2_W1H);
        uint4* d1l = (uint4*)(smem + SM2_W1L);
        uint4* d2h = (uint4*)(smem + SM2_W2H);
        uint4* d2l = (uint4*)(smem + SM2_W2L);
        for (int i = tid; i < 1024; i += 512) {
            d1h[i] = s1h[i]; d1l[i] = s1l[i]; d2h[i] = s2h[i]; d2l[i] = s2l[i];
        }
    }
    float* sb1 = (float*)(smem + SM2_SB1);
    float* slg = (float*)(smem + SM2_SLG);
    float* slb = (float*)(smem + SM2_SLB);
    float* sb2 = (float*)(smem + SM2_SB2);
    float* sng = (float*)(smem + SM2_SNG);
    float* snb = (float*)(smem + SM2_SNB);
    if (tid < 128) { sb1[tid] = b1[tid]; slg[tid] = lg[tid]; slb[tid] = lb[tid]; }
    if (tid < 64) {
        sb2[tid] = b2[tid];
        sng[tid] = writez ? ng[tid] : 0.f;
        snb[tid] = writez ? nb[tid] : 0.f;
    }

    int q = lane & 3;
    int g = lane >> 2;
    int nGroups = N >> 4;
    int grp = blockIdx.x * 16 + w;
    bool act = grp < nGroups;
    int n0 = grp << 4;

    // prefetch first y batch BEFORE the sync so it overlaps weight staging
    const float2* yr1 = (const float2*)(g_y + (size_t)(n0 + g) * 64);
    const float2* yr2 = (const float2*)(g_y + (size_t)(n0 + g + 8) * 64);
    float2 fa0, fa1, fb0, fb1;
    if (act) { fa0 = yr1[q]; fa1 = yr1[4 + q]; fb0 = yr2[q]; fb1 = yr2[4 + q]; }

    __syncthreads();
    if (!act) return;

    // ldmatrix B addressing
    int lane7 = lane & 7;
    int laneb3 = (lane >> 3) & 1;
    int laneb4 = lane >> 4;
    uint32_t mask = (uint32_t)lane7 << 4;
    uint32_t bRow = (uint32_t)(laneb4 * 8 + lane7) * 128u;
    uint32_t bSeg = (uint32_t)laneb3 * 16u;

    float2* h2 = (float2*)g_h;
    float2* z2 = (float2*)g_z;

    // ---- GEMM1: C1[16x128] = A1[16x64] @ W1T^T (rolling y prefetch) ----
    float acc[16][4];
#pragma unroll
    for (int i = 0; i < 16; i++) { acc[i][0] = 0.f; acc[i][1] = 0.f; acc[i][2] = 0.f; acc[i][3] = 0.f; }
#pragma unroll
    for (int kk = 0; kk < 4; kk++) {
        float2 p0 = fa0, p1 = fa1, p2 = fb0, p3 = fb1;
        if (kk < 3) {
            fa0 = yr1[8 * (kk + 1) + q];
            fa1 = yr1[8 * (kk + 1) + 4 + q];
            fb0 = yr2[8 * (kk + 1) + q];
            fb1 = yr2[8 * (kk + 1) + 4 + q];
        }
        float h00 = bfhi(p0.x), h01 = bfhi(p0.y);
        float h10 = bfhi(p1.x), h11 = bfhi(p1.y);
        float h20 = bfhi(p2.x), h21 = bfhi(p2.y);
        float h30 = bfhi(p3.x), h31 = bfhi(p3.y);
        uint32_t ah[4], al[4];
        ah[0] = packbf(h00, h01); ah[1] = packbf(h20, h21);
        ah[2] = packbf(h10, h11); ah[3] = packbf(h30, h31);
        al[0] = packbf(p0.x - h00, p0.y - h01);
        al[1] = packbf(p2.x - h20, p2.y - h21);
        al[2] = packbf(p1.x - h10, p1.y - h11);
        al[3] = packbf(p3.x - h30, p3.y - h31);
#pragma unroll
        for (int n16 = 0; n16 < 8; n16++) {
            uint32_t bo = (uint32_t)n16 * 2048u + bRow + (((uint32_t)kk * 32u + bSeg) ^ mask);
            uint32_t bh[4], bl[4];
            ldsm4(bh, sbase + SM2_W1H + bo);
            ldsm4(bl, sbase + SM2_W1L + bo);
            float* c0 = acc[2 * n16];
            float* c1 = acc[2 * n16 + 1];
            mma16816(c0, ah, bh[0], bh[1]);
            mma16816(c1, ah, bh[2], bh[3]);
            mma16816(c0, ah, bl[0], bl[1]);
            mma16816(c1, ah, bl[2], bl[3]);
            mma16816(c0, al, bh[0], bh[1]);
            mma16816(c1, al, bh[2], bh[3]);
        }
    }
    // ---- epilogue1: bias + LN + relu, in-register (quad reduce) ----
    {
        float sA = 0.f, sB = 0.f, qA = 0.f, qB = 0.f;
#pragma unroll
        for (int idx = 0; idx < 16; idx++) {
            int col = idx * 8 + 2 * q;
            float bb0 = sb1[col], bb1 = sb1[col + 1];
            acc[idx][0] += bb0; acc[idx][1] += bb1;
            acc[idx][2] += bb0; acc[idx][3] += bb1;
            sA += acc[idx][0] + acc[idx][1];
            sB += acc[idx][2] + acc[idx][3];
            qA = fmaf(acc[idx][0], acc[idx][0], qA);
            qA = fmaf(acc[idx][1], acc[idx][1], qA);
            qB = fmaf(acc[idx][2], acc[idx][2], qB);
            qB = fmaf(acc[idx][3], acc[idx][3], qB);
        }
        sA = quadSum(sA); sB = quadSum(sB);
        qA = quadSum(qA); qB = quadSum(qB);
        float meanA = sA * (1.0f / 128.0f);
        float meanB = sB * (1.0f / 128.0f);
        float varA = qA * (1.0f / 128.0f) - meanA * meanA;
        float varB = qB * (1.0f / 128.0f) - meanB * meanB;
        float rstdA = rsqrtf(varA + 1e-5f);
        float rstdB = rsqrtf(varB + 1e-5f);
#pragma unroll
        for (int idx = 0; idx < 16; idx++) {
            int col = idx * 8 + 2 * q;
            float g0 = slg[col], g1 = slg[col + 1];
            float bb0 = slb[col], bb1 = slb[col + 1];
            acc[idx][0] = fmaxf(fmaf((acc[idx][0] - meanA) * rstdA, g0, bb0), 0.f);
            acc[idx][1] = fmaxf(fmaf((acc[idx][1] - meanA) * rstdA, g1, bb1), 0.f);
            acc[idx][2] = fmaxf(fmaf((acc[idx][2] - meanB) * rstdB, g0, bb0), 0.f);
            acc[idx][3] = fmaxf(fmaf((acc[idx][3] - meanB) * rstdB, g1, bb1), 0.f);
        }
    }
    // ---- GEMM2: C2[16x64] = A2[16x128] @ W2T^T ; A2 frags from acc regs ----
    float acc2[8][4];
#pragma unroll
    for (int i = 0; i < 8; i++) { acc2[i][0] = 0.f; acc2[i][1] = 0.f; acc2[i][2] = 0.f; acc2[i][3] = 0.f; }
#pragma unroll
    for (int kk = 0; kk < 8; kk++) {
        int i0 = 2 * kk, i1 = 2 * kk + 1;
        float h00 = bfhi(acc[i0][0]), h01 = bfhi(acc[i0][1]);
        float h20 = bfhi(acc[i0][2]), h21 = bfhi(acc[i0][3]);
        float h10 = bfhi(acc[i1][0]), h11 = bfhi(acc[i1][1]);
        float h30 = bfhi(acc[i1][2]), h31 = bfhi(acc[i1][3]);
        uint32_t ah[4], al[4];
        ah[0] = packbf(h00, h01); ah[1] = packbf(h20, h21);
        ah[2] = packbf(h10, h11); ah[3] = packbf(h30, h31);
        al[0] = packbf(acc[i0][0] - h00, acc[i0][1] - h01);
        al[1] = packbf(acc[i0][2] - h20, acc[i0][3] - h21);
        al[2] = packbf(acc[i1][0] - h10, acc[i1][1] - h11);
        al[3] = packbf(acc[i1][2] - h30, acc[i1][3] - h31);
        uint32_t halfW = (kk < 4) ? 0u : 8192u;
        uint32_t kk2 = (uint32_t)(kk & 3);
#pragma unroll
        for (int n16 = 0; n16 < 4; n16++) {
            uint32_t bo = (uint32_t)n16 * 2048u + bRow + ((kk2 * 32u + bSeg) ^ mask) + halfW;
            uint32_t bh[4], bl[4];
            ldsm4(bh, sbase + SM2_W2H + bo);
            ldsm4(bl, sbase + SM2_W2L + bo);
            float* c0 = acc2[2 * n16];
            float* c1 = acc2[2 * n16 + 1];
            mma16816(c0, ah, bh[0], bh[1]);
            mma16816(c1, ah, bh[2], bh[3]);
            mma16816(c0, ah, bl[0], bl[1]);
            mma16816(c1, ah, bl[2], bl[3]);
            mma16816(c0, al, bh[0], bh[1]);
            mma16816(c1, al, bh[2], bh[3]);
        }
    }
    // ---- epilogue2: bias + residual -> h ; fused next-layer prenorm -> z ----
    {
        int nodeA = n0 + g, nodeB = n0 + g + 8;
        float sA = 0.f, sB = 0.f, qA = 0.f, qB = 0.f;
#pragma unroll
        for (int idx = 0; idx < 8; idx++) {
            int col = idx * 8 + 2 * q;
            float bb0 = sb2[col], bb1 = sb2[col + 1];
            float oA0 = acc2[idx][0] + bb0, oA1 = acc2[idx][1] + bb1;
            float oB0 = acc2[idx][2] + bb0, oB1 = acc2[idx][3] + bb1;
            int iA = nodeA * 32 + (col >> 1);
            int iB = nodeB * 32 + (col >> 1);
            if (add) {
                float2 rA = h2[iA], rB = h2[iB];
                oA0 += rA.x; oA1 += rA.y;
                oB0 += rB.x; oB1 += rB.y;
            }
            h2[iA] = make_float2(oA0, oA1);
            h2[iB] = make_float2(oB0, oB1);
            acc2[idx][0] = oA0; acc2[idx][1] = oA1;
            acc2[idx][2] = oB0; acc2[idx][3] = oB1;
            sA += oA0 + oA1; sB += oB0 + oB1;
            qA = fmaf(oA0, oA0, qA); qA = fmaf(oA1, oA1, qA);
            qB = fmaf(oB0, oB0, qB); qB = fmaf(oB1, oB1, qB);
        }
        if (writez) {
            sA = quadSum(sA); sB = quadSum(sB);
            qA = quadSum(qA); qB = quadSum(qB);
            float meanA = sA * (1.0f / 64.0f);
            float meanB = sB * (1.0f / 64.0f);
            float varA = qA * (1.0f / 64.0f) - meanA * meanA;
            float varB = qB * (1.0f / 64.0f) - meanB * meanB;
            float rstdA = rsqrtf(varA + 1e-5f);
            float rstdB = rsqrtf(varB + 1e-5f);
#pragma unroll
            for (int idx = 0; idx < 8; idx++) {
                int col = idx * 8 + 2 * q;
                float g0 = sng[col], g1 = sng[col + 1];
                float bb0 = snb[col], bb1 = snb[col + 1];
                float2 zA, zB;
                zA.x = fmaxf(fmaf((acc2[idx][0] - meanA) * rstdA, g0, bb0), 0.f);
                zA.y = fmaxf(fmaf((acc2[idx][1] - meanA) * rstdA, g1, bb1), 0.f);
                zB.x = fmaxf(fmaf((acc2[idx][2] - meanB) * rstdB, g0, bb0), 0.f);
                zB.y = fmaxf(fmaf((acc2[idx][3] - meanB) * rstdB, g1, bb1), 0.f);
                z2[nodeA * 32 + (col >> 1)] = zA;
                z2[nodeB * 32 + (col >> 1)] = zB;
            }
        }
    }
}

// ---------------- Head: LN -> pool -> fc -> bn -> l2norm ----------------
__global__ void __launch_bounds__(256) head_kernel(
    const float* __restrict__ ng, const float* __restrict__ nb,
    const float* __restrict__ fcW, const float* __restrict__ fcb,
    const float* __restrict__ bg, const float* __restrict__ bb,
    const float* __restrict__ bm, const float* __restrict__ bv,
    float* __restrict__ out, int NP) {
    __shared__ float shp[17 * 64];
    __shared__ float spool[6 * 64];
    __shared__ float sf[1536];
    __shared__ float sred[8];
    __shared__ float sinv;
    int p = blockIdx.x;
    int tid = threadIdx.x;
    int w = tid >> 5, lane = tid & 31;
    const float2* __restrict__ h2 = (const float2*)g_h;
    float2 gg = ((const float2*)ng)[lane];
    float2 gb = ((const float2*)nb)[lane];
    for (int i = w; i < 17; i += 8) {
        float2 v = h2[(p * 17 + i) * 32 + lane];
        float mean = warpSum(v.x + v.y) * (1.0f / 64.0f);
        float dx = v.x - mean, dy = v.y - mean;
        float var = warpSum(dx * dx + dy * dy) * (1.0f / 64.0f);
        float rstd = rsqrtf(var + 1e-5f);
        shp[i * 64 + 2 * lane]     = fmaxf(fmaf(dx * rstd, gg.x, gb.x), 0.0f);
        shp[i * 64 + 2 * lane + 1] = fmaxf(fmaf(dy * rstd, gg.y, gb.y), 0.0f);
    }
    __syncthreads();
    {
        const int ga[6] = {0, 0, 11, 0, 5, 11};
        const int gbx[6] = {17, 11, 17, 5, 11, 17};
        for (int i = tid; i < 384; i += 256) {
            int s = i >> 6, c = i & 63;
            float acc = 0;
            for (int kp = ga[s]; kp < gbx[s]; kp++) acc += shp[kp * 64 + c];
            spool[i] = acc / (float)(gbx[s] - ga[s]);
        }
    }
    __syncthreads();
    float sq = 0;
#pragma unroll
    for (int s = 0; s < 6; s++) {
        int o = s * 256 + tid;
        float acc = fcb[o];
        const float* wp = fcW + s * 16384 + tid;
        const float* pp = spool + s * 64;
#pragma unroll 8
        for (int c = 0; c < 64; c++) acc = fmaf(pp[c], wp[c * 256], acc);
        float val = fmaf((acc - bm[o]) * rsqrtf(bv[o] + 1e-5f), bg[o], bb[o]);
        sf[o] = val;
        sq = fmaf(val, val, sq);
    }
    sq = warpSum(sq);
    if (lane == 0) sred[w] = sq;
    __syncthreads();
    if (tid == 0) {
        float tot = 0;
#pragma unroll
        for (int i = 0; i < 8; i++) tot += sred[i];
        sinv = 1.0f / fmaxf(sqrtf(tot), 1e-12f);
    }
    __syncthreads();
    float inv = sinv;
#pragma unroll
    for (int s = 0; s < 6; s++) {
        int o = s * 256 + tid;
        out[p * 1536 + o] = sf[o] * inv;
    }
}

// ---------------- Host orchestration ----------------
extern "C" void kernel_launch(void* const* d_in, const int* in_sizes, int n_in,
                              void* d_out, int out_size) {
    const float* x      = (const float*)d_in[0];
    const int*   ei     = (const int*)d_in[1];
    const float* enc_W  = (const float*)d_in[2];
    const float* enc_b  = (const float*)d_in[3];
    const float* t      = (const float*)d_in[4];
    const float* mlp_W1 = (const float*)d_in[5];
    const float* mlp_b1 = (const float*)d_in[6];
    const float* ln_g   = (const float*)d_in[7];
    const float* ln_b   = (const float*)d_in[8];
    const float* mlp_W2 = (const float*)d_in[9];
    const float* mlp_b2 = (const float*)d_in[10];
    const float* norm_g = (const float*)d_in[11];
    const float* norm_b = (const float*)d_in[12];
    const float* fc_W   = (const float*)d_in[13];
    const float* fc_b   = (const float*)d_in[14];
    const float* bn_g   = (const float*)d_in[15];
    const float* bn_b   = (const float*)d_in[16];
    const float* bn_m   = (const float*)d_in[17];
    const float* bn_v   = (const float*)d_in[18];
    float* out = (float*)d_out;

    int N = in_sizes[0] / 3;
    int E = in_sizes[1] / 2;
    int NP = N / 17;
    const int L = 56;

    cudaFuncSetAttribute(mlp_kernel, cudaFuncAttributeMaxDynamicSharedMemorySize, SM2_TOTAL);

    // CSR build (dst-sorted)
    zero_kernel<<<(N + 255) / 256, 256>>>(N);
    count_kernel<<<(E + 255) / 256, 256>>>(ei + E, E);
    scan_kernel<<<1, 1024>>>(N);
    scatter_kernel<<<(E + 255) / 256, 256>>>(ei, ei + E, E);

    // degree-sorted node permutation (descending): balances aggr warps per block
    dcount_kernel<<<(N + 255) / 256, 256>>>(N);
    dscan_kernel<<<1, 256>>>();
    dscatter_kernel<<<(N + 255) / 256, 256>>>(N);

    // weight prep (bf16 split + swizzle, all layers)
    prep_kernel<<<(2 * LMAX * 8192 + 255) / 256, 256>>>(mlp_W1, mlp_W2);

    // Encoder -> z (layer 0 aggregates raw encoder output; needs relu)
    enc_kernel<<<(N * 64 + 255) / 256, 256>>>(x, enc_W, enc_b, N);

    const int MGRID = 148;
    int aggrBlocks = (N + 7) / 8;   // one warp per node

    for (int l = 0; l < L; l++) {
        if (l == 0) aggr_kernel<true><<<aggrBlocks, 256>>>(t, l, N);
        else        aggr_kernel<false><<<aggrBlocks, 256>>>(t, l, N);
        int last = (l == L - 1);
        mlp_kernel<<<MGRID, 512, SM2_TOTAL>>>(
            mlp_b1 + l * 128, ln_g + l * 128, ln_b + l * 128, mlp_b2 + l * 64,
            norm_g + (last ? 0 : (l + 1) * 64), norm_b + (last ? 0 : (l + 1) * 64),
            l, N, l != 0, !last);
    }

    // Head (applies final LN with layer-0 norm params internally)
    head_kernel<<<NP, 256>>>(norm_g, norm_b, fc_W, fc_b, bn_g, bn_b, bn_m, bn_v, out, NP);
}